// round 15
// baseline (speedup 1.0000x reference)
#include <cuda_runtime.h>
#include <cuda_bf16.h>
#include <math.h>
#include <stdint.h>

#define BB 64
#define HH 1024
#define VV 50257
#define TT 7
#define G3 3072
#define KK 1024

#define NT 128
#define BKC 16
#define NBLKV ((VV + NT - 1) / NT)   // 393
#define NBLK2 ((NBLKV + 1) / 2)      // 197 paired-tile blocks
#define SPLITK 4
#define KC (KK / SPLITK)             // 256

#define KB 64
#define NCHT 16
#define NCH_G (KC / KB)              // 4

// ---- GRU smem layout ----
#define BUF0 1024
#define BUFSZ 49152
#define OF_WLO 16384
#define OF_BHI 32768
#define OF_BLO 40960
#define SM_TC (BUF0 + 2 * BUFSZ)     // 99328 -> 2 CTAs/SM

// ---- logits smem layout ----
#define LW0 1024
#define LH0 (LW0 + 2 * 32768)

#define SWZ(o) ((o) ^ (((o) >> 3) & 0x70))
#define IDESC_BF16 ((1u<<4)|(1u<<7)|(1u<<10)|((64u/8u)<<17)|((128u/16u)<<24))

#if defined(__CUDA_ARCH_FEAT_SM103_ALL) || defined(__CUDA_ARCH_FEAT_SM100_ALL) || \
    defined(__CUDA_ARCH_SPECIFIC__) || defined(__CUDA_ARCH_FAMILY_SPECIFIC__)
#define HAS_TC 1
#else
#define HAS_TC 0
#endif

#if defined(__CUDA_ARCH__) && __CUDA_ARCH__ >= 900
#define GDC_WAIT()   asm volatile("griddepcontrol.wait;" ::: "memory")
#define GDC_LAUNCH() asm volatile("griddepcontrol.launch_dependents;" ::: "memory")
#else
#define GDC_WAIT()
#define GDC_LAUNCH()
#endif

typedef unsigned long long ull;

// ------------------------- device scratch ---------------------------------
__device__ float g_h[BB * HH];
__device__ __align__(16) __nv_bfloat16 g_hhi[BB * HH];
__device__ __align__(16) __nv_bfloat16 g_hlo[BB * HH];
__device__ __align__(16) __nv_bfloat16 g_lw_hi[(size_t)VV * KK];
__device__ __align__(16) __nv_bfloat16 g_lw_lo[(size_t)VV * KK];
__device__ __align__(16) __nv_bfloat16 g_wi_hi[G3 * KK];
__device__ __align__(16) __nv_bfloat16 g_wi_lo[G3 * KK];
__device__ __align__(16) __nv_bfloat16 g_wh_hi[G3 * KK];
__device__ __align__(16) __nv_bfloat16 g_wh_lo[G3 * KK];
__device__ float g_gi[SPLITK * BB * G3];
__device__ float g_gh[SPLITK * BB * G3];
__device__ int   g_x[BB];
__device__ float g_pmax[NBLKV * BB];
__device__ int   g_pidx[NBLKV * BB];
__device__ float g_psum[NBLKV * BB];
__device__ float g_lse[2 * BB];

// ------------------------- helpers ----------------------------------------
__device__ __forceinline__ uint32_t smem_u32(const void* p) {
    uint32_t a;
    asm("{ .reg .u64 t1; cvta.to.shared.u64 t1, %1; cvt.u32.u64 %0, t1; }"
        : "=r"(a) : "l"(p));
    return a;
}
__device__ __forceinline__ uint32_t packbf2(float x, float y) {
    __nv_bfloat16 a = __float2bfloat16(x), b = __float2bfloat16(y);
    return ((uint32_t)__bfloat16_as_ushort(b) << 16) | (uint32_t)__bfloat16_as_ushort(a);
}
__device__ __forceinline__ ull pk2(float x, float y) {
    ull r; asm("mov.b64 %0, {%1,%2};" : "=l"(r) : "f"(x), "f"(y)); return r;
}
__device__ __forceinline__ void upk2(ull v, float &x, float &y) {
    asm("mov.b64 {%0,%1}, %2;" : "=f"(x), "=f"(y) : "l"(v));
}
__device__ __forceinline__ void fma2(ull &d, ull a, ull b) {
    asm("fma.rn.f32x2 %0, %1, %2, %0;" : "+l"(d) : "l"(a), "l"(b));
}
__device__ __forceinline__ void mbar_wait(uint32_t mbar, uint32_t parity) {
    uint32_t done;
    asm volatile("{ .reg .pred p; mbarrier.try_wait.parity.acquire.cta.shared::cta.b64 p, [%1], %2; selp.b32 %0,1,0,p; }"
                 : "=r"(done) : "r"(mbar), "r"(parity) : "memory");
    if (!done) {
        asm volatile("{ .reg .pred P1; WL%=: mbarrier.try_wait.parity.acquire.cta.shared::cta.b64 P1, [%0], %1, 0x989680; @P1 bra.uni WD%=; bra.uni WL%=; WD%=: }"
                     :: "r"(mbar), "r"(parity) : "memory");
    }
}
__device__ __forceinline__ void cpasync16(uint32_t dst, const void* src) {
    asm volatile("cp.async.cg.shared.global [%0], [%1], 16;" :: "r"(dst), "l"(src) : "memory");
}

// ------------------------- FFMA2 GEMM core (fallback path) -----------------
__device__ __forceinline__ void gemm_core(
    const float* __restrict__ A, const float* __restrict__ W,
    int n0, int k0, int ksteps, int nmax, ull acc[8][4],
    const int* xidx)
{
    __shared__ __align__(16) float As[BKC][64];
    __shared__ __align__(16) float Ws[BKC][NT];
    const int tid = threadIdx.x;
    const int v_idx = tid & 15;
    const int m_idx = tid >> 4;

#pragma unroll
    for (int i = 0; i < 8; i++)
#pragma unroll
        for (int p = 0; p < 4; p++) acc[i][p] = 0ULL;

    for (int kb = 0; kb < ksteps; kb += BKC) {
        const int kg = k0 + kb;
#pragma unroll
        for (int r = 0; r < 2; r++) {
            int idx = tid + r * 128;
            int m = idx >> 2;
            int kk = (idx & 3) << 2;
            size_t arow = xidx ? (size_t)xidx[m] : (size_t)m;
            float4 a = *(const float4*)(A + arow * KK + kg + kk);
            if (xidx) {
                a.x = fmaxf(a.x, 0.f); a.y = fmaxf(a.y, 0.f);
                a.z = fmaxf(a.z, 0.f); a.w = fmaxf(a.w, 0.f);
            }
            As[kk + 0][m] = a.x; As[kk + 1][m] = a.y;
            As[kk + 2][m] = a.z; As[kk + 3][m] = a.w;
        }
#pragma unroll
        for (int r = 0; r < 4; r++) {
            int idx = tid + r * 128;
            int n = idx >> 2;
            int kk = (idx & 3) << 2;
            int row = n0 + n; if (row > nmax - 1) row = nmax - 1;
            float4 w = *(const float4*)(W + (size_t)row * KK + kg + kk);
            Ws[kk + 0][n] = w.x; Ws[kk + 1][n] = w.y;
            Ws[kk + 2][n] = w.z; Ws[kk + 3][n] = w.w;
        }
        __syncthreads();
#pragma unroll
        for (int k = 0; k < BKC; k++) {
            float4 a0 = *(const float4*)&As[k][m_idx * 8];
            float4 a1 = *(const float4*)&As[k][m_idx * 8 + 4];
            float4 w0 = *(const float4*)&Ws[k][v_idx * 8];
            float4 w1 = *(const float4*)&Ws[k][v_idx * 8 + 4];
            ull wp0 = pk2(w0.x, w0.y), wp1 = pk2(w0.z, w0.w);
            ull wp2 = pk2(w1.x, w1.y), wp3 = pk2(w1.z, w1.w);
            float av[8] = {a0.x, a0.y, a0.z, a0.w, a1.x, a1.y, a1.z, a1.w};
#pragma unroll
            for (int i = 0; i < 8; i++) {
                ull aa = pk2(av[i], av[i]);
                fma2(acc[i][0], aa, wp0);
                fma2(acc[i][1], aa, wp1);
                fma2(acc[i][2], aa, wp2);
                fma2(acc[i][3], aa, wp3);
            }
        }
        __syncthreads();
    }
}

// ------------------------- tc machinery (HAS_TC only) ----------------------
#if HAS_TC
__device__ __forceinline__ void mma3_at(uint32_t sbase, uint32_t tmem_acc, int cc,
                                        uint32_t wOff, uint32_t hOff, int first)
{
    const uint64_t DBASE = ((uint64_t)2 << 61) | ((uint64_t)1 << 46) |
                           ((uint64_t)64 << 32) | ((uint64_t)1 << 16);
    uint64_t dwh = DBASE | (uint64_t)(((sbase + wOff) >> 4) & 0x3FFF);
    uint64_t dwl = DBASE | (uint64_t)(((sbase + wOff + 16384) >> 4) & 0x3FFF);
    uint64_t dbh = DBASE | (uint64_t)(((sbase + hOff) >> 4) & 0x3FFF);
    uint64_t dbl = DBASE | (uint64_t)(((sbase + hOff + 8192) >> 4) & 0x3FFF);
    asm volatile("fence.proxy.async.shared::cta;" ::: "memory");
#pragma unroll
    for (int ks = 0; ks < 4; ks++) {
        uint32_t en0 = (first && ks == 0) ? 0u : 1u;
        asm volatile("{ .reg .pred p; setp.ne.u32 p, %4, 0;\n\t"
                     "tcgen05.mma.cta_group::1.kind::f16 [%0], %1, %2, %3, {%5,%5,%5,%5}, p; }"
                     :: "r"(tmem_acc), "l"(dwh + ks * 2), "l"(dbh + ks * 2), "r"(IDESC_BF16), "r"(en0), "r"(0u) : "memory");
        asm volatile("{ .reg .pred p; setp.ne.u32 p, %4, 0;\n\t"
                     "tcgen05.mma.cta_group::1.kind::f16 [%0], %1, %2, %3, {%5,%5,%5,%5}, p; }"
                     :: "r"(tmem_acc), "l"(dwh + ks * 2), "l"(dbl + ks * 2), "r"(IDESC_BF16), "r"(1u), "r"(0u) : "memory");
        asm volatile("{ .reg .pred p; setp.ne.u32 p, %4, 0;\n\t"
                     "tcgen05.mma.cta_group::1.kind::f16 [%0], %1, %2, %3, {%5,%5,%5,%5}, p; }"
                     :: "r"(tmem_acc), "l"(dwl + ks * 2), "l"(dbh + ks * 2), "r"(IDESC_BF16), "r"(1u), "r"(0u) : "memory");
    }
    asm volatile("tcgen05.commit.cta_group::1.mbarrier::arrive::one.shared::cluster.b64 [%0];"
                 :: "r"(sbase + 8 + (uint32_t)(cc & 1) * 8) : "memory");
}

// ---- GRU staging ----------------------------------------------------------
__device__ __forceinline__ void stage_gru_w(
    uint32_t sbase, int cc,
    const __nv_bfloat16* __restrict__ whi, const __nv_bfloat16* __restrict__ wlo,
    int wrow0, int kg, int tid)
{
    uint32_t base = sbase + BUF0 + (uint32_t)(cc & 1) * BUFSZ;
#pragma unroll
    for (int i = 0; i < 8; i++) {
        int g = tid + i * 128;
        int row = g >> 3, c8 = g & 7;
        size_t so = (size_t)(wrow0 + row) * KK + kg + c8 * 8;
        uint32_t dsw = SWZ((uint32_t)(row * 128 + c8 * 16));
        cpasync16(base + dsw, whi + so);
        cpasync16(base + OF_WLO + dsw, wlo + so);
    }
}

template<bool EMBED>
__device__ __forceinline__ void stage_gru_b(
    char* smem, uint32_t sbase, int cc,
    const __nv_bfloat16* __restrict__ bhi, const __nv_bfloat16* __restrict__ blo,
    const float* __restrict__ embp, int kg, int tid)
{
    uint32_t base = sbase + BUF0 + (uint32_t)(cc & 1) * BUFSZ;
    if (EMBED) {
        char* buf = smem + BUF0 + (cc & 1) * BUFSZ;
#pragma unroll
        for (int i = 0; i < 4; i++) {
            int g = tid + i * 128;
            int row = g >> 3, c8 = g & 7;
            const float* src = embp + (size_t)g_x[row] * KK + kg + c8 * 8;
            float4 a = __ldg((const float4*)src);
            float4 b = __ldg((const float4*)(src + 4));
            a.x = fmaxf(a.x, 0.f); a.y = fmaxf(a.y, 0.f);
            a.z = fmaxf(a.z, 0.f); a.w = fmaxf(a.w, 0.f);
            b.x = fmaxf(b.x, 0.f); b.y = fmaxf(b.y, 0.f);
            b.z = fmaxf(b.z, 0.f); b.w = fmaxf(b.w, 0.f);
            uint4 hp, lp;
            hp.x = packbf2(a.x, a.y); hp.y = packbf2(a.z, a.w);
            hp.z = packbf2(b.x, b.y); hp.w = packbf2(b.z, b.w);
            float r0 = a.x - __bfloat162float(__float2bfloat16(a.x));
            float r1 = a.y - __bfloat162float(__float2bfloat16(a.y));
            float r2 = a.z - __bfloat162float(__float2bfloat16(a.z));
            float r3 = a.w - __bfloat162float(__float2bfloat16(a.w));
            float r4 = b.x - __bfloat162float(__float2bfloat16(b.x));
            float r5 = b.y - __bfloat162float(__float2bfloat16(b.y));
            float r6 = b.z - __bfloat162float(__float2bfloat16(b.z));
            float r7 = b.w - __bfloat162float(__float2bfloat16(b.w));
            lp.x = packbf2(r0, r1); lp.y = packbf2(r2, r3);
            lp.z = packbf2(r4, r5); lp.w = packbf2(r6, r7);
            uint32_t dsw = SWZ((uint32_t)(row * 128 + c8 * 16));
            *(uint4*)(buf + OF_BHI + dsw) = hp;
            *(uint4*)(buf + OF_BLO + dsw) = lp;
        }
    } else {
#pragma unroll
        for (int i = 0; i < 4; i++) {
            int g = tid + i * 128;
            int row = g >> 3, c8 = g & 7;
            size_t so = (size_t)row * KK + kg + c8 * 8;
            uint32_t dsw = SWZ((uint32_t)(row * 128 + c8 * 16));
            cpasync16(base + OF_BHI + dsw, bhi + so);
            cpasync16(base + OF_BLO + dsw, blo + so);
        }
    }
}

template<int NCHUNKS, bool EMBED>
__device__ __forceinline__ void tc_pipe_gru(
    char* smem, uint32_t sbase, uint32_t tmem,
    const __nv_bfloat16* __restrict__ whi, const __nv_bfloat16* __restrict__ wlo,
    const __nv_bfloat16* __restrict__ bhi, const __nv_bfloat16* __restrict__ blo,
    const float* __restrict__ embp,
    int row0, int kg0, int tid, int wid)
{
    stage_gru_w(sbase, 0, whi, wlo, row0, kg0, tid);
    GDC_WAIT();
    stage_gru_b<EMBED>(smem, sbase, 0, bhi, blo, embp, kg0, tid);
    asm volatile("cp.async.commit_group;" ::: "memory");
    for (int c = 0; c < NCHUNKS; c++) {
        if (c + 1 < NCHUNKS) {
            if (c + 1 >= 2) {
                int idx = (c - 1) >> 1;
                mbar_wait(sbase + 8 + (uint32_t)((c + 1) & 1) * 8, (uint32_t)(idx & 1));
            }
            stage_gru_w(sbase, c + 1, whi, wlo, row0, kg0 + (c + 1) * KB, tid);
            stage_gru_b<EMBED>(smem, sbase, c + 1, bhi, blo, embp, kg0 + (c + 1) * KB, tid);
            asm volatile("cp.async.commit_group;" ::: "memory");
            asm volatile("cp.async.wait_group 1;" ::: "memory");
        } else {
            asm volatile("cp.async.wait_group 0;" ::: "memory");
        }
        __syncthreads();
        if (wid == 0) {
            uint32_t is1;
            asm volatile("{ .reg .pred p; elect.sync _|p, 0xFFFFFFFF; selp.b32 %0,1,0,p; }" : "=r"(is1));
            if (is1) {
                uint32_t b = BUF0 + (uint32_t)(c & 1) * BUFSZ;
                mma3_at(sbase, tmem, c, b, b + OF_BHI, c == 0);
            }
        }
    }
    uint32_t fp = (uint32_t)(((NCHUNKS / 2) - 1) & 1);
    mbar_wait(sbase + 8, fp);
    mbar_wait(sbase + 16, fp);
    asm volatile("tcgen05.fence::after_thread_sync;" ::: "memory");
}

// ---- logits stages --------------------------------------------------------
__device__ __forceinline__ void stage_log_w(uint32_t sbase, int cc,
                                            int wrow0, int kg, int tid)
{
    uint32_t base = sbase + LW0 + (uint32_t)(cc & 1) * 32768;
#pragma unroll
    for (int i = 0; i < 8; i++) {
        int g = tid + i * 128;
        int row = g >> 3, c8 = g & 7;
        int r = wrow0 + row; if (r >= VV) r = VV - 1;
        size_t so = (size_t)r * KK + kg + c8 * 8;
        uint32_t dsw = SWZ((uint32_t)(row * 128 + c8 * 16));
        cpasync16(base + dsw, g_lw_hi + so);
        cpasync16(base + 16384 + dsw, g_lw_lo + so);
    }
}
__device__ __forceinline__ void stage_log_h(uint32_t sbase, int kc, int kg, int tid)
{
    uint32_t base = sbase + LH0 + (uint32_t)(kc & 1) * 16384;
#pragma unroll
    for (int i = 0; i < 4; i++) {
        int g = tid + i * 128;
        int row = g >> 3, c8 = g & 7;
        size_t so = (size_t)row * KK + kg + c8 * 8;
        uint32_t dsw = SWZ((uint32_t)(row * 128 + c8 * 16));
        cpasync16(base + dsw, g_hhi + so);
        cpasync16(base + 8192 + dsw, g_hlo + so);
    }
}

__device__ __forceinline__ void tc_pipe_log(
    uint32_t sbase, uint32_t tmem, int tile0, int ntiles, int tid, int wid)
{
    const int NCH = ntiles * NCHT;
    stage_log_w(sbase, 0, tile0 * NT, 0, tid);
    GDC_WAIT();
    stage_log_h(sbase, 0, 0, tid);
    asm volatile("cp.async.commit_group;" ::: "memory");
    for (int cc = 0; cc < NCH; cc++) {
        int tile = (ntiles == 2) ? (cc & 1) : 0;
        int kc = (ntiles == 2) ? (cc >> 1) : cc;
        if (cc + 1 < NCH) {
            int nc = cc + 1;
            int ntile = (ntiles == 2) ? (nc & 1) : 0;
            int nkc = (ntiles == 2) ? (nc >> 1) : nc;
            if (nc >= 2) {
                int idx = (cc - 1) >> 1;
                mbar_wait(sbase + 8 + (uint32_t)(nc & 1) * 8, (uint32_t)(idx & 1));
            }
            stage_log_w(sbase, nc, (tile0 + ntile) * NT, nkc * KB, tid);
            if (ntile == 0 && nkc > 0) stage_log_h(sbase, nkc, nkc * KB, tid);
            asm volatile("cp.async.commit_group;" ::: "memory");
            asm volatile("cp.async.wait_group 1;" ::: "memory");
        } else {
            asm volatile("cp.async.wait_group 0;" ::: "memory");
        }
        __syncthreads();
        if (wid == 0) {
            uint32_t is1;
            asm volatile("{ .reg .pred p; elect.sync _|p, 0xFFFFFFFF; selp.b32 %0,1,0,p; }" : "=r"(is1));
            if (is1) {
                uint32_t wOff = LW0 + (uint32_t)(cc & 1) * 32768;
                uint32_t hOff = LH0 + (uint32_t)(kc & 1) * 16384;
                mma3_at(sbase, tmem + (uint32_t)tile * 64, cc, wOff, hOff, kc == 0);
            }
        }
    }
    uint32_t fp = (uint32_t)(((NCH / 2) - 1) & 1);
    mbar_wait(sbase + 8, fp);
    mbar_wait(sbase + 16, fp);
    asm volatile("tcgen05.fence::after_thread_sync;" ::: "memory");
}

#define TC_PROLOG(sbase, tmem, ncols)                                                        \
    if (wid == 0) {                                                                          \
        asm volatile("tcgen05.alloc.cta_group::1.sync.aligned.shared::cta.b32 [%0], %1;"     \
                     :: "r"(sbase), "r"((uint32_t)(ncols)) : "memory");                      \
        asm volatile("tcgen05.relinquish_alloc_permit.cta_group::1.sync.aligned;");          \
    }                                                                                        \
    if (tid == 0) {                                                                          \
        asm volatile("mbarrier.init.shared.b64 [%0], %1;" :: "r"(sbase + 8), "r"(1u) : "memory");  \
        asm volatile("mbarrier.init.shared.b64 [%0], %1;" :: "r"(sbase + 16), "r"(1u) : "memory"); \
    }                                                                                        \
    __syncthreads();                                                                         \
    asm volatile("ld.shared.b32 %0, [%1];" : "=r"(tmem) : "r"(sbase));

#define TC_EPILOG(sbase, tmem, ncols)                                                        \
    __syncthreads();                                                                         \
    if (tid == 0) {                                                                          \
        asm volatile("mbarrier.inval.shared.b64 [%0];" :: "r"(sbase + 8) : "memory");        \
        asm volatile("mbarrier.inval.shared.b64 [%0];" :: "r"(sbase + 16) : "memory");       \
    }                                                                                        \
    __syncthreads();                                                                         \
    if (wid == 0)                                                                            \
        asm volatile("tcgen05.dealloc.cta_group::1.sync.aligned.b32 %0, %1;" :: "r"(tmem), "r"((uint32_t)(ncols)));

#define LDTM32(r, addr) \
    asm volatile("tcgen05.ld.sync.aligned.32x32b.x32.b32 " \
        "{%0,%1,%2,%3,%4,%5,%6,%7,%8,%9,%10,%11,%12,%13,%14,%15," \
        "%16,%17,%18,%19,%20,%21,%22,%23,%24,%25,%26,%27,%28,%29,%30,%31}, [%32];" \
        : "=r"((r)[0]),"=r"((r)[1]),"=r"((r)[2]),"=r"((r)[3]),"=r"((r)[4]),"=r"((r)[5]),"=r"((r)[6]),"=r"((r)[7]), \
          "=r"((r)[8]),"=r"((r)[9]),"=r"((r)[10]),"=r"((r)[11]),"=r"((r)[12]),"=r"((r)[13]),"=r"((r)[14]),"=r"((r)[15]), \
          "=r"((r)[16]),"=r"((r)[17]),"=r"((r)[18]),"=r"((r)[19]),"=r"((r)[20]),"=r"((r)[21]),"=r"((r)[22]),"=r"((r)[23]), \
          "=r"((r)[24]),"=r"((r)[25]),"=r"((r)[26]),"=r"((r)[27]),"=r"((r)[28]),"=r"((r)[29]),"=r"((r)[30]),"=r"((r)[31]) \
        : "r"(addr))
#endif // HAS_TC

// ------------------------- small kernels ----------------------------------
__global__ void prep_lw_kernel(const float* __restrict__ lin_w)
{
    const size_t NW = (size_t)VV * KK / 4;
    size_t i = (size_t)blockIdx.x * 256 + threadIdx.x;
    if (i >= NW) return;
    float4 v = ((const float4*)lin_w)[i];
    uint2 hp, lp;
    hp.x = packbf2(v.x, v.y);
    hp.y = packbf2(v.z, v.w);
    float r0 = v.x - __bfloat162float(__float2bfloat16(v.x));
    float r1 = v.y - __bfloat162float(__float2bfloat16(v.y));
    float r2 = v.z - __bfloat162float(__float2bfloat16(v.z));
    float r3 = v.w - __bfloat162float(__float2bfloat16(v.w));
    lp.x = packbf2(r0, r1);
    lp.y = packbf2(r2, r3);
    *(uint2*)(g_lw_hi + i * 4) = hp;
    *(uint2*)(g_lw_lo + i * 4) = lp;
}

__global__ void prep_gru_kernel(const float* __restrict__ w_ih,
                                const float* __restrict__ w_hh)
{
    const size_t NG = (size_t)G3 * KK / 4;
    size_t i = (size_t)blockIdx.x * 256 + threadIdx.x;
    const float* src; __nv_bfloat16 *dhi, *dlo; size_t off;
    if (i < NG)          { src = w_ih; dhi = g_wi_hi; dlo = g_wi_lo; off = i; }
    else if (i < 2 * NG) { src = w_hh; dhi = g_wh_hi; dlo = g_wh_lo; off = i - NG; }
    else return;
    float4 v = ((const float4*)src)[off];
    uint2 hp, lp;
    hp.x = packbf2(v.x, v.y);
    hp.y = packbf2(v.z, v.w);
    float r0 = v.x - __bfloat162float(__float2bfloat16(v.x));
    float r1 = v.y - __bfloat162float(__float2bfloat16(v.y));
    float r2 = v.z - __bfloat162float(__float2bfloat16(v.z));
    float r3 = v.w - __bfloat162float(__float2bfloat16(v.w));
    lp.x = packbf2(r0, r1);
    lp.y = packbf2(r2, r3);
    *(uint2*)(dhi + off * 4) = hp;
    *(uint2*)(dlo + off * 4) = lp;
}

__global__ void init_kernel(const int* __restrict__ target,
                            const float* __restrict__ enc)
{
    int i = blockIdx.x * 256 + threadIdx.x;
    if (i < BB) g_x[i] = target[i * TT];
    if (i < BB * HH) {
        float h = enc[i];
        g_h[i] = h;
        __nv_bfloat16 hb = __float2bfloat16(h);
        g_hhi[i] = hb;
        g_hlo[i] = __float2bfloat16(h - __bfloat162float(hb));
    }
}

// ------------------------- GRU GEMM ----------------------------------------
__global__ void __launch_bounds__(128) gru_tc_kernel(
    const float* __restrict__ w_ih, const float* __restrict__ w_hh,
    const float* __restrict__ emb)
{
    const int tid = threadIdx.x, wid = tid >> 5;
    const int z = blockIdx.z, ksl = blockIdx.y;
    const int row0 = blockIdx.x * 128;
    GDC_LAUNCH();
#if HAS_TC
    extern __shared__ char smem[];
    uint32_t sbase = smem_u32(smem);
    uint32_t tmem;
    TC_PROLOG(sbase, tmem, 64);
    if (z) {
        tc_pipe_gru<NCH_G, false>(smem, sbase, tmem, g_wh_hi, g_wh_lo,
                                  g_hhi, g_hlo, (const float*)0,
                                  row0, ksl * KC, tid, wid);
    } else {
        tc_pipe_gru<NCH_G, true>(smem, sbase, tmem, g_wi_hi, g_wi_lo,
                                 (const __nv_bfloat16*)0, (const __nv_bfloat16*)0, emb,
                                 row0, ksl * KC, tid, wid);
    }

    uint32_t d0[32], d1[32];
    LDTM32(d0, tmem);
    LDTM32(d1, tmem + 32);
    asm volatile("tcgen05.wait::ld.sync.aligned;" ::: "memory");

    float* out = (z ? g_gh : g_gi) + ksl * (BB * G3);
    int n = row0 + tid;
#pragma unroll
    for (int m = 0; m < 32; m++) out[m * G3 + n] = __uint_as_float(d0[m]);
#pragma unroll
    for (int m = 0; m < 32; m++) out[(m + 32) * G3 + n] = __uint_as_float(d1[m]);

    TC_EPILOG(sbase, tmem, 64);
#else
    GDC_WAIT();
    const float* A = z ? g_h : emb;
    const float* W = z ? w_hh : w_ih;
    float* out = (z ? g_gh : g_gi) + ksl * (BB * G3);
    ull acc[8][4];
    gemm_core(A, W, row0, ksl * KC, KC, G3, acc, z ? (const int*)0 : g_x);
    int v_idx = tid & 15, m_idx = tid >> 4;
#pragma unroll
    for (int i = 0; i < 8; i++) {
        int m = m_idx * 8 + i;
#pragma unroll
        for (int p = 0; p < 4; p++) {
            float lo, hi; upk2(acc[i][p], lo, hi);
            int n = row0 + v_idx * 8 + p * 2;
            *(float2*)(out + m * G3 + n) = make_float2(lo, hi);
        }
    }
#endif
}

// split-K reduce + GRU gates + h update + bf16 split of h
__global__ void gate_kernel(const float* __restrict__ b_ih,
                            const float* __restrict__ b_hh)
{
    GDC_WAIT();
    GDC_LAUNCH();
    int i = blockIdx.x * 256 + threadIdx.x;
    if (i >= BB * HH) return;
    int m = i >> 10, j = i & 1023;
    float gir = 0, giz = 0, gin = 0, ghr = 0, ghz = 0, ghn = 0;
#pragma unroll
    for (int s = 0; s < SPLITK; s++) {
        const float* gi = g_gi + s * BB * G3 + m * G3;
        const float* gh = g_gh + s * BB * G3 + m * G3;
        gir += gi[j]; giz += gi[HH + j]; gin += gi[2 * HH + j];
        ghr += gh[j]; ghz += gh[HH + j]; ghn += gh[2 * HH + j];
    }
    gir += b_ih[j]; giz += b_ih[HH + j]; gin += b_ih[2 * HH + j];
    ghr += b_hh[j]; ghz += b_hh[HH + j]; ghn += b_hh[2 * HH + j];
    float r = 1.f / (1.f + expf(-(gir + ghr)));
    float z = 1.f / (1.f + expf(-(giz + ghz)));
    float n = tanhf(gin + r * ghn);
    float hn = (1.f - z) * n + z * g_h[i];
    g_h[i] = hn;
    __nv_bfloat16 hb = __float2bfloat16(hn);
    g_hhi[i] = hb;
    g_hlo[i] = __float2bfloat16(hn - __bfloat162float(hb));
}

// ------------------------- logits ------------------------------------------
__global__ void __launch_bounds__(128) logits_tc_kernel(
    const float* __restrict__ lin_w, const float* __restrict__ lin_b,
    float* __restrict__ logits, int t)
{
    const int tile0 = blockIdx.x * 2;
    const int ntiles = (tile0 + 1 < NBLKV) ? 2 : 1;
    GDC_LAUNCH();
#if HAS_TC
    extern __shared__ char smem[];
    uint32_t sbase = smem_u32(smem);
    const int tid = threadIdx.x, wid = tid >> 5;
    uint32_t tmem;
    TC_PROLOG(sbase, tmem, 128);

    tc_pipe_log(sbase, tmem, tile0, ntiles, tid, wid);

    for (int sub = 0; sub < ntiles; sub++) {
        const int tile = tile0 + sub;
        const int n0 = tile * NT;
        const int v = n0 + tid;
        const bool valid = v < VV;
        float bias = lin_b[valid ? v : VV - 1];
        uint32_t d0[32], d1[32];
        LDTM32(d0, tmem + (uint32_t)sub * 64);
        LDTM32(d1, tmem + (uint32_t)sub * 64 + 32);
        asm volatile("tcgen05.wait::ld.sync.aligned;" ::: "memory");

        float vals[64];
#pragma unroll
        for (int j = 0; j < 32; j++) {
            vals[j] = __uint_as_float(d0[j]) + bias;
            vals[32 + j] = __uint_as_float(d1[j]) + bias;
        }

#pragma unroll
        for (int m = 0; m < 64; m++)
            if (valid) logits[((size_t)m * TT + t) * VV + v] = vals[m];

        float* ts = (float*)(smem + LW0);
        __syncthreads();
#pragma unroll
        for (int m = 0; m < 64; m++)
            ts[tid * 65 + m] = valid ? vals[m] : -INFINITY;
        __syncthreads();

        int m = tid >> 1, half = tid & 1;
        float best = -INFINITY; int bi = 0;
        for (int j = 0; j < 64; j++) {
            float x = ts[(half * 64 + j) * 65 + m];
            if (x > best) { best = x; bi = half * 64 + j; }
        }
        float s = 0.f;
        if (best > -INFINITY)
            for (int j = 0; j < 64; j++)
                s += __expf(ts[(half * 64 + j) * 65 + m] - best);

        float ob = __shfl_xor_sync(0xffffffffu, best, 1);
        int   oi = __shfl_xor_sync(0xffffffffu, bi, 1);
        float os = __shfl_xor_sync(0xffffffffu, s, 1);
        float M2 = fmaxf(best, ob);
        float S2 = 0.f;
        if (best > -INFINITY) S2 += s * __expf(best - M2);
        if (ob   > -INFINITY) S2 += os * __expf(ob - M2);
        int gbi = bi;
        if (ob > best || (ob == best && oi < bi)) gbi = oi;
        if (half == 0) {
            g_pmax[tile * BB + m] = M2;
            g_pidx[tile * BB + m] = n0 + gbi;
            g_psum[tile * BB + m] = S2;
        }
    }

    TC_EPILOG(sbase, tmem, 128);
#else
    GDC_WAIT();
    for (int sub = 0; sub < ntiles; sub++) {
        int tile = tile0 + sub;
        if (tile >= NBLKV) break;
        int n0 = tile * NT;
        ull acc[8][4];
        gemm_core(g_h, lin_w, n0, 0, KK, VV, acc, (const int*)0);
        int v_idx = threadIdx.x & 15, m_idx = threadIdx.x >> 4;
        int vb = n0 + v_idx * 8;

        float bias[8];
#pragma unroll
        for (int j = 0; j < 8; j++) {
            int v = vb + j;
            bias[j] = lin_b[v < VV ? v : VV - 1];
        }

#pragma unroll
        for (int i = 0; i < 8; i++) {
            int m = m_idx * 8 + i;
            float vals[8];
#pragma unroll
            for (int p = 0; p < 4; p++) {
                float lo, hi; upk2(acc[i][p], lo, hi);
                vals[p * 2]     = lo + bias[p * 2];
                vals[p * 2 + 1] = hi + bias[p * 2 + 1];
            }
            size_t base = ((size_t)m * TT + t) * VV;
#pragma unroll
            for (int j = 0; j < 8; j++) {
                int v = vb + j;
                if (v < VV) logits[base + v] = vals[j];
            }
            float vmax = -INFINITY; int vidx = 0;
#pragma unroll
            for (int j = 0; j < 8; j++) {
                int v = vb + j;
                if (v < VV && vals[j] > vmax) { vmax = vals[j]; vidx = v; }
            }
            float ssum = 0.f;
            if (vmax > -INFINITY) {
#pragma unroll
                for (int j = 0; j < 8; j++) {
                    int v = vb + j;
                    if (v < VV) ssum += expf(vals[j] - vmax);
                }
            }
#pragma unroll
            for (int off = 8; off >= 1; off >>= 1) {
                float om = __shfl_xor_sync(0xffffffffu, vmax, off);
                int   oi = __shfl_xor_sync(0xffffffffu, vidx, off);
                float os = __shfl_xor_sync(0xffffffffu, ssum, off);
                float nm = fmaxf(vmax, om);
                float ns = 0.f;
                if (vmax > -INFINITY) ns += ssum * expf(vmax - nm);
                if (om   > -INFINITY) ns += os   * expf(om  - nm);
                if (om > vmax || (om == vmax && oi < vidx)) vidx = oi;
                vmax = nm; ssum = ns;
            }
            if (v_idx == 0) {
                g_pmax[tile * BB + m] = vmax;
                g_pidx[tile * BB + m] = vidx;
                g_psum[tile * BB + m] = ssum;
            }
        }
        __syncthreads();
    }
#endif
}

// per-m reduce of block partials -> argmax token + lse (double buffered)
__global__ void __launch_bounds__(128) reduce_kernel(int par)
{
    GDC_WAIT();
    GDC_LAUNCH();
    int m = blockIdx.x;
    int tid = threadIdx.x;
    float M = -INFINITY, S = 0.f, bv = -INFINITY; int bi = 0;
    for (int b = tid; b < NBLKV; b += 128) {
        float pm = g_pmax[b * BB + m];
        int   pi = g_pidx[b * BB + m];
        float ps = g_psum[b * BB + m];
        if (pm > bv || (pm == bv && pi < bi)) { bv = pm; bi = pi; }
        float nm = fmaxf(M, pm);
        float ns = 0.f;
        if (M  > -INFINITY) ns += S  * expf(M  - nm);
        if (pm > -INFINITY) ns += ps * expf(pm - nm);
        M = nm; S = ns;
    }
    __shared__ float sM[128], sS[128], sV[128];
    __shared__ int sI[128];
    sM[tid] = M; sS[tid] = S; sV[tid] = bv; sI[tid] = bi;
    __syncthreads();
    for (int w = 64; w >= 1; w >>= 1) {
        if (tid < w) {
            float om = sM[tid + w], os = sS[tid + w], ov = sV[tid + w];
            int oi = sI[tid + w];
            if (ov > sV[tid] || (ov == sV[tid] && oi < sI[tid])) { sV[tid] = ov; sI[tid] = oi; }
            float nm = fmaxf(sM[tid], om);
            float ns = 0.f;
            if (sM[tid] > -INFINITY) ns += sS[tid] * expf(sM[tid] - nm);
            if (om      > -INFINITY) ns += os      * expf(om      - nm);
            sM[tid] = nm; sS[tid] = ns;
        }
        __syncthreads();
    }
    if (tid == 0) { g_x[m] = sI[0]; g_lse[par * BB + m] = sM[0] + logf(sS[0]); }
}

// logp writer (side stream; off the recurrence critical path)
#define VCHK 3968
#define NVCHK ((VV + VCHK - 1) / VCHK)   // 13
__global__ void __launch_bounds__(256) logp_kernel(
    const float* __restrict__ logits, float* __restrict__ logp, int t, int par)
{
    const int m = blockIdx.y;
    const int ck = blockIdx.x;
    const int tid = threadIdx.x;
    float lse = g_lse[par * BB + m];
    size_t base = ((size_t)m * TT + t) * VV;
    int vend = (ck + 1) * VCHK; if (vend > VV) vend = VV;
    for (int v = ck * VCHK + tid; v < vend; v += 256)
        logp[base + v] = logits[base + v] - lse;
}

// ------------------------- launch -----------------------------------------
extern "C" void kernel_launch(void* const* d_in, const int* in_sizes, int n_in,
                              void* d_out, int out_size)
{
    const int*   target = (const int*)  d_in[0];
    const float* enc    = (const float*)d_in[1];
    const float* emb    = (const float*)d_in[2];
    const float* w_ih   = (const float*)d_in[3];
    const float* w_hh   = (const float*)d_in[4];
    const float* b_ih   = (const float*)d_in[5];
    const float* b_hh   = (const float*)d_in[6];
    const float* lin_w  = (const float*)d_in[7];
    const float* lin_b  = (const float*)d_in[8];

    float* logp   = (float*)d_out;                 // (B, T, V)
    float* logits = logp + (size_t)BB * TT * VV;   // (B, T, V)

    // one-time resource setup (avoids per-call allocations that trip the
    // harness leak tracker; same pattern as one-time cudaFuncSetAttribute)
    static cudaStream_t s2;
    static cudaEvent_t e0, eLw, eFork, eJoin;
    static int inited = 0;
    if (!inited) {
        cudaFuncSetAttribute(logits_tc_kernel,
                             cudaFuncAttributeMaxDynamicSharedMemorySize, SM_TC);
        cudaFuncSetAttribute(gru_tc_kernel,
                             cudaFuncAttributeMaxDynamicSharedMemorySize, SM_TC);
        cudaStreamCreateWithFlags(&s2, cudaStreamNonBlocking);
        cudaEventCreateWithFlags(&e0, cudaEventDisableTiming);
        cudaEventCreateWithFlags(&eLw, cudaEventDisableTiming);
        cudaEventCreateWithFlags(&eFork, cudaEventDisableTiming);
        cudaEventCreateWithFlags(&eJoin, cudaEventDisableTiming);
        inited = 1;
    }

    cudaLaunchAttribute pdlAttr[1];
    pdlAttr[0].id = cudaLaunchAttributeProgrammaticStreamSerialization;
    pdlAttr[0].val.programmaticStreamSerializationAllowed = 1;

    // fork: lin_w prep on s2
    cudaEventRecord(e0, 0);
    cudaStreamWaitEvent(s2, e0, 0);
    const size_t nw4 = (size_t)VV * KK / 4;
    prep_lw_kernel<<<(unsigned)((nw4 + 255) / 256), 256, 0, s2>>>(lin_w);
    cudaEventRecord(eLw, s2);

    const size_t ng4 = 2 * (size_t)G3 * KK / 4;
    prep_gru_kernel<<<(unsigned)((ng4 + 255) / 256), 256>>>(w_ih, w_hh);
    init_kernel<<<(BB * HH + 255) / 256, 256>>>(target, enc);

    for (int t = 0; t < TT; t++) {
        {
            cudaLaunchConfig_t cfg = {};
            cfg.gridDim = dim3(G3 / NT, SPLITK, 2);
            cfg.blockDim = dim3(128);
            cfg.dynamicSmemBytes = SM_TC;
            cfg.stream = 0;
            cfg.attrs = pdlAttr; cfg.numAttrs = 1;
            cudaLaunchKernelEx(&cfg, gru_tc_kernel, w_ih, w_hh, emb);
        }
        // fork logp(t-1) AFTER gru(t): overlaps gate+logits, not gru
        if (t > 0) {
            cudaEventRecord(eFork, 0);
            cudaStreamWaitEvent(s2, eFork, 0);
            logp_kernel<<<dim3(NVCHK, BB), 256, 0, s2>>>(logits, logp, t - 1, (t - 1) & 1);
        }
        {
            cudaLaunchConfig_t cfg = {};
            cfg.gridDim = dim3((BB * HH + 255) / 256);
            cfg.blockDim = dim3(256);
            cfg.stream = 0;
            cfg.attrs = pdlAttr; cfg.numAttrs = 1;
            cudaLaunchKernelEx(&cfg, gate_kernel, b_ih, b_hh);
        }
        if (t == 0) cudaStreamWaitEvent(0, eLw, 0);
        {
            cudaLaunchConfig_t cfg = {};
            cfg.gridDim = dim3(NBLK2);
            cfg.blockDim = dim3(128);
            cfg.dynamicSmemBytes = SM_TC;
            cfg.stream = 0;
            cfg.attrs = pdlAttr; cfg.numAttrs = 1;
            cudaLaunchKernelEx(&cfg, logits_tc_kernel, lin_w, lin_b, logits, t);
        }
        {
            cudaLaunchConfig_t cfg = {};
            cfg.gridDim = dim3(BB);
            cfg.blockDim = dim3(128);
            cfg.stream = 0;
            cfg.attrs = pdlAttr; cfg.numAttrs = 1;
            int par = t & 1;
            cudaLaunchKernelEx(&cfg, reduce_kernel, par);
        }
    }
    // final logp for t = TT-1 on s2, then join
    cudaEventRecord(eFork, 0);
    cudaStreamWaitEvent(s2, eFork, 0);
    logp_kernel<<<dim3(NVCHK, BB), 256, 0, s2>>>(logits, logp, TT - 1, (TT - 1) & 1);
    cudaEventRecord(eJoin, s2);
    cudaStreamWaitEvent(0, eJoin, 0);
}

// round 16
// speedup vs baseline: 1.0119x; 1.0119x over previous
#include <cuda_runtime.h>
#include <cuda_bf16.h>
#include <math.h>
#include <stdint.h>

#define BB 64
#define HH 1024
#define VV 50257
#define TT 7
#define G3 3072
#define KK 1024

#define NT 128
#define BKC 16
#define NBLKV ((VV + NT - 1) / NT)   // 393
#define NBLK2 ((NBLKV + 1) / 2)      // 197 paired-tile blocks
#define SPLITK 4
#define KC (KK / SPLITK)             // 256

#define KB 64
#define NCHT 16
#define NCH_G (KC / KB)              // 4

// ---- GRU smem layout ----
#define BUF0 1024
#define BUFSZ 49152
#define OF_WLO 16384
#define OF_BHI 32768
#define OF_BLO 40960
#define SM_TC (BUF0 + 2 * BUFSZ)     // 99328 -> 2 CTAs/SM

// ---- logits smem layout ----
#define LW0 1024
#define LH0 (LW0 + 2 * 32768)

#define SWZ(o) ((o) ^ (((o) >> 3) & 0x70))
#define IDESC_BF16 ((1u<<4)|(1u<<7)|(1u<<10)|((64u/8u)<<17)|((128u/16u)<<24))

#if defined(__CUDA_ARCH_FEAT_SM103_ALL) || defined(__CUDA_ARCH_FEAT_SM100_ALL) || \
    defined(__CUDA_ARCH_SPECIFIC__) || defined(__CUDA_ARCH_FAMILY_SPECIFIC__)
#define HAS_TC 1
#else
#define HAS_TC 0
#endif

#if defined(__CUDA_ARCH__) && __CUDA_ARCH__ >= 900
#define GDC_WAIT()   asm volatile("griddepcontrol.wait;" ::: "memory")
#define GDC_LAUNCH() asm volatile("griddepcontrol.launch_dependents;" ::: "memory")
#else
#define GDC_WAIT()
#define GDC_LAUNCH()
#endif

typedef unsigned long long ull;

// ------------------------- device scratch ---------------------------------
__device__ float g_h[BB * HH];
__device__ __align__(16) __nv_bfloat16 g_hhi[BB * HH];
__device__ __align__(16) __nv_bfloat16 g_hlo[BB * HH];
__device__ __align__(16) __nv_bfloat16 g_lw_hi[(size_t)VV * KK];
__device__ __align__(16) __nv_bfloat16 g_lw_lo[(size_t)VV * KK];
__device__ __align__(16) __nv_bfloat16 g_wi_hi[G3 * KK];
__device__ __align__(16) __nv_bfloat16 g_wi_lo[G3 * KK];
__device__ __align__(16) __nv_bfloat16 g_wh_hi[G3 * KK];
__device__ __align__(16) __nv_bfloat16 g_wh_lo[G3 * KK];
__device__ float g_gi[SPLITK * BB * G3];
__device__ float g_gh[SPLITK * BB * G3];
__device__ int   g_x[BB];
__device__ float g_pmax[NBLKV * BB];
__device__ int   g_pidx[NBLKV * BB];
__device__ float g_psum[NBLKV * BB];
__device__ float g_lse[2 * BB];

// ------------------------- helpers ----------------------------------------
__device__ __forceinline__ uint32_t smem_u32(const void* p) {
    uint32_t a;
    asm("{ .reg .u64 t1; cvta.to.shared.u64 t1, %1; cvt.u32.u64 %0, t1; }"
        : "=r"(a) : "l"(p));
    return a;
}
__device__ __forceinline__ uint32_t packbf2(float x, float y) {
    __nv_bfloat16 a = __float2bfloat16(x), b = __float2bfloat16(y);
    return ((uint32_t)__bfloat16_as_ushort(b) << 16) | (uint32_t)__bfloat16_as_ushort(a);
}
__device__ __forceinline__ ull pk2(float x, float y) {
    ull r; asm("mov.b64 %0, {%1,%2};" : "=l"(r) : "f"(x), "f"(y)); return r;
}
__device__ __forceinline__ void upk2(ull v, float &x, float &y) {
    asm("mov.b64 {%0,%1}, %2;" : "=f"(x), "=f"(y) : "l"(v));
}
__device__ __forceinline__ void fma2(ull &d, ull a, ull b) {
    asm("fma.rn.f32x2 %0, %1, %2, %0;" : "+l"(d) : "l"(a), "l"(b));
}
__device__ __forceinline__ void mbar_wait(uint32_t mbar, uint32_t parity) {
    uint32_t done;
    asm volatile("{ .reg .pred p; mbarrier.try_wait.parity.acquire.cta.shared::cta.b64 p, [%1], %2; selp.b32 %0,1,0,p; }"
                 : "=r"(done) : "r"(mbar), "r"(parity) : "memory");
    if (!done) {
        asm volatile("{ .reg .pred P1; WL%=: mbarrier.try_wait.parity.acquire.cta.shared::cta.b64 P1, [%0], %1, 0x989680; @P1 bra.uni WD%=; bra.uni WL%=; WD%=: }"
                     :: "r"(mbar), "r"(parity) : "memory");
    }
}
__device__ __forceinline__ void cpasync16(uint32_t dst, const void* src) {
    asm volatile("cp.async.cg.shared.global [%0], [%1], 16;" :: "r"(dst), "l"(src) : "memory");
}

// ------------------------- FFMA2 GEMM core (fallback path) -----------------
__device__ __forceinline__ void gemm_core(
    const float* __restrict__ A, const float* __restrict__ W,
    int n0, int k0, int ksteps, int nmax, ull acc[8][4],
    const int* xidx)
{
    __shared__ __align__(16) float As[BKC][64];
    __shared__ __align__(16) float Ws[BKC][NT];
    const int tid = threadIdx.x;
    const int v_idx = tid & 15;
    const int m_idx = tid >> 4;

#pragma unroll
    for (int i = 0; i < 8; i++)
#pragma unroll
        for (int p = 0; p < 4; p++) acc[i][p] = 0ULL;

    for (int kb = 0; kb < ksteps; kb += BKC) {
        const int kg = k0 + kb;
#pragma unroll
        for (int r = 0; r < 2; r++) {
            int idx = tid + r * 128;
            int m = idx >> 2;
            int kk = (idx & 3) << 2;
            size_t arow = xidx ? (size_t)xidx[m] : (size_t)m;
            float4 a = *(const float4*)(A + arow * KK + kg + kk);
            if (xidx) {
                a.x = fmaxf(a.x, 0.f); a.y = fmaxf(a.y, 0.f);
                a.z = fmaxf(a.z, 0.f); a.w = fmaxf(a.w, 0.f);
            }
            As[kk + 0][m] = a.x; As[kk + 1][m] = a.y;
            As[kk + 2][m] = a.z; As[kk + 3][m] = a.w;
        }
#pragma unroll
        for (int r = 0; r < 4; r++) {
            int idx = tid + r * 128;
            int n = idx >> 2;
            int kk = (idx & 3) << 2;
            int row = n0 + n; if (row > nmax - 1) row = nmax - 1;
            float4 w = *(const float4*)(W + (size_t)row * KK + kg + kk);
            Ws[kk + 0][n] = w.x; Ws[kk + 1][n] = w.y;
            Ws[kk + 2][n] = w.z; Ws[kk + 3][n] = w.w;
        }
        __syncthreads();
#pragma unroll
        for (int k = 0; k < BKC; k++) {
            float4 a0 = *(const float4*)&As[k][m_idx * 8];
            float4 a1 = *(const float4*)&As[k][m_idx * 8 + 4];
            float4 w0 = *(const float4*)&Ws[k][v_idx * 8];
            float4 w1 = *(const float4*)&Ws[k][v_idx * 8 + 4];
            ull wp0 = pk2(w0.x, w0.y), wp1 = pk2(w0.z, w0.w);
            ull wp2 = pk2(w1.x, w1.y), wp3 = pk2(w1.z, w1.w);
            float av[8] = {a0.x, a0.y, a0.z, a0.w, a1.x, a1.y, a1.z, a1.w};
#pragma unroll
            for (int i = 0; i < 8; i++) {
                ull aa = pk2(av[i], av[i]);
                fma2(acc[i][0], aa, wp0);
                fma2(acc[i][1], aa, wp1);
                fma2(acc[i][2], aa, wp2);
                fma2(acc[i][3], aa, wp3);
            }
        }
        __syncthreads();
    }
}

// ------------------------- tc machinery (HAS_TC only) ----------------------
#if HAS_TC
__device__ __forceinline__ void mma3_at(uint32_t sbase, uint32_t tmem_acc, int cc,
                                        uint32_t wOff, uint32_t hOff, int first)
{
    const uint64_t DBASE = ((uint64_t)2 << 61) | ((uint64_t)1 << 46) |
                           ((uint64_t)64 << 32) | ((uint64_t)1 << 16);
    uint64_t dwh = DBASE | (uint64_t)(((sbase + wOff) >> 4) & 0x3FFF);
    uint64_t dwl = DBASE | (uint64_t)(((sbase + wOff + 16384) >> 4) & 0x3FFF);
    uint64_t dbh = DBASE | (uint64_t)(((sbase + hOff) >> 4) & 0x3FFF);
    uint64_t dbl = DBASE | (uint64_t)(((sbase + hOff + 8192) >> 4) & 0x3FFF);
    asm volatile("fence.proxy.async.shared::cta;" ::: "memory");
#pragma unroll
    for (int ks = 0; ks < 4; ks++) {
        uint32_t en0 = (first && ks == 0) ? 0u : 1u;
        asm volatile("{ .reg .pred p; setp.ne.u32 p, %4, 0;\n\t"
                     "tcgen05.mma.cta_group::1.kind::f16 [%0], %1, %2, %3, {%5,%5,%5,%5}, p; }"
                     :: "r"(tmem_acc), "l"(dwh + ks * 2), "l"(dbh + ks * 2), "r"(IDESC_BF16), "r"(en0), "r"(0u) : "memory");
        asm volatile("{ .reg .pred p; setp.ne.u32 p, %4, 0;\n\t"
                     "tcgen05.mma.cta_group::1.kind::f16 [%0], %1, %2, %3, {%5,%5,%5,%5}, p; }"
                     :: "r"(tmem_acc), "l"(dwh + ks * 2), "l"(dbl + ks * 2), "r"(IDESC_BF16), "r"(1u), "r"(0u) : "memory");
        asm volatile("{ .reg .pred p; setp.ne.u32 p, %4, 0;\n\t"
                     "tcgen05.mma.cta_group::1.kind::f16 [%0], %1, %2, %3, {%5,%5,%5,%5}, p; }"
                     :: "r"(tmem_acc), "l"(dwl + ks * 2), "l"(dbh + ks * 2), "r"(IDESC_BF16), "r"(1u), "r"(0u) : "memory");
    }
    asm volatile("tcgen05.commit.cta_group::1.mbarrier::arrive::one.shared::cluster.b64 [%0];"
                 :: "r"(sbase + 8 + (uint32_t)(cc & 1) * 8) : "memory");
}

// ---- GRU staging ----------------------------------------------------------
__device__ __forceinline__ void stage_gru_w(
    uint32_t sbase, int cc,
    const __nv_bfloat16* __restrict__ whi, const __nv_bfloat16* __restrict__ wlo,
    int wrow0, int kg, int tid)
{
    uint32_t base = sbase + BUF0 + (uint32_t)(cc & 1) * BUFSZ;
#pragma unroll
    for (int i = 0; i < 8; i++) {
        int g = tid + i * 128;
        int row = g >> 3, c8 = g & 7;
        size_t so = (size_t)(wrow0 + row) * KK + kg + c8 * 8;
        uint32_t dsw = SWZ((uint32_t)(row * 128 + c8 * 16));
        cpasync16(base + dsw, whi + so);
        cpasync16(base + OF_WLO + dsw, wlo + so);
    }
}

template<bool EMBED>
__device__ __forceinline__ void stage_gru_b(
    char* smem, uint32_t sbase, int cc,
    const __nv_bfloat16* __restrict__ bhi, const __nv_bfloat16* __restrict__ blo,
    const float* __restrict__ embp, int kg, int tid)
{
    uint32_t base = sbase + BUF0 + (uint32_t)(cc & 1) * BUFSZ;
    if (EMBED) {
        char* buf = smem + BUF0 + (cc & 1) * BUFSZ;
#pragma unroll
        for (int i = 0; i < 4; i++) {
            int g = tid + i * 128;
            int row = g >> 3, c8 = g & 7;
            const float* src = embp + (size_t)g_x[row] * KK + kg + c8 * 8;
            float4 a = __ldg((const float4*)src);
            float4 b = __ldg((const float4*)(src + 4));
            a.x = fmaxf(a.x, 0.f); a.y = fmaxf(a.y, 0.f);
            a.z = fmaxf(a.z, 0.f); a.w = fmaxf(a.w, 0.f);
            b.x = fmaxf(b.x, 0.f); b.y = fmaxf(b.y, 0.f);
            b.z = fmaxf(b.z, 0.f); b.w = fmaxf(b.w, 0.f);
            uint4 hp, lp;
            hp.x = packbf2(a.x, a.y); hp.y = packbf2(a.z, a.w);
            hp.z = packbf2(b.x, b.y); hp.w = packbf2(b.z, b.w);
            float r0 = a.x - __bfloat162float(__float2bfloat16(a.x));
            float r1 = a.y - __bfloat162float(__float2bfloat16(a.y));
            float r2 = a.z - __bfloat162float(__float2bfloat16(a.z));
            float r3 = a.w - __bfloat162float(__float2bfloat16(a.w));
            float r4 = b.x - __bfloat162float(__float2bfloat16(b.x));
            float r5 = b.y - __bfloat162float(__float2bfloat16(b.y));
            float r6 = b.z - __bfloat162float(__float2bfloat16(b.z));
            float r7 = b.w - __bfloat162float(__float2bfloat16(b.w));
            lp.x = packbf2(r0, r1); lp.y = packbf2(r2, r3);
            lp.z = packbf2(r4, r5); lp.w = packbf2(r6, r7);
            uint32_t dsw = SWZ((uint32_t)(row * 128 + c8 * 16));
            *(uint4*)(buf + OF_BHI + dsw) = hp;
            *(uint4*)(buf + OF_BLO + dsw) = lp;
        }
    } else {
#pragma unroll
        for (int i = 0; i < 4; i++) {
            int g = tid + i * 128;
            int row = g >> 3, c8 = g & 7;
            size_t so = (size_t)row * KK + kg + c8 * 8;
            uint32_t dsw = SWZ((uint32_t)(row * 128 + c8 * 16));
            cpasync16(base + OF_BHI + dsw, bhi + so);
            cpasync16(base + OF_BLO + dsw, blo + so);
        }
    }
}

template<int NCHUNKS, bool EMBED>
__device__ __forceinline__ void tc_pipe_gru(
    char* smem, uint32_t sbase, uint32_t tmem,
    const __nv_bfloat16* __restrict__ whi, const __nv_bfloat16* __restrict__ wlo,
    const __nv_bfloat16* __restrict__ bhi, const __nv_bfloat16* __restrict__ blo,
    const float* __restrict__ embp,
    int row0, int kg0, int tid, int wid)
{
    stage_gru_w(sbase, 0, whi, wlo, row0, kg0, tid);
    GDC_WAIT();
    stage_gru_b<EMBED>(smem, sbase, 0, bhi, blo, embp, kg0, tid);
    asm volatile("cp.async.commit_group;" ::: "memory");
    for (int c = 0; c < NCHUNKS; c++) {
        if (c + 1 < NCHUNKS) {
            if (c + 1 >= 2) {
                int idx = (c - 1) >> 1;
                mbar_wait(sbase + 8 + (uint32_t)((c + 1) & 1) * 8, (uint32_t)(idx & 1));
            }
            stage_gru_w(sbase, c + 1, whi, wlo, row0, kg0 + (c + 1) * KB, tid);
            stage_gru_b<EMBED>(smem, sbase, c + 1, bhi, blo, embp, kg0 + (c + 1) * KB, tid);
            asm volatile("cp.async.commit_group;" ::: "memory");
            asm volatile("cp.async.wait_group 1;" ::: "memory");
        } else {
            asm volatile("cp.async.wait_group 0;" ::: "memory");
        }
        __syncthreads();
        if (wid == 0) {
            uint32_t is1;
            asm volatile("{ .reg .pred p; elect.sync _|p, 0xFFFFFFFF; selp.b32 %0,1,0,p; }" : "=r"(is1));
            if (is1) {
                uint32_t b = BUF0 + (uint32_t)(c & 1) * BUFSZ;
                mma3_at(sbase, tmem, c, b, b + OF_BHI, c == 0);
            }
        }
    }
    uint32_t fp = (uint32_t)(((NCHUNKS / 2) - 1) & 1);
    mbar_wait(sbase + 8, fp);
    mbar_wait(sbase + 16, fp);
    asm volatile("tcgen05.fence::after_thread_sync;" ::: "memory");
}

// ---- logits stages --------------------------------------------------------
__device__ __forceinline__ void stage_log_w(uint32_t sbase, int cc,
                                            int wrow0, int kg, int tid)
{
    uint32_t base = sbase + LW0 + (uint32_t)(cc & 1) * 32768;
#pragma unroll
    for (int i = 0; i < 8; i++) {
        int g = tid + i * 128;
        int row = g >> 3, c8 = g & 7;
        int r = wrow0 + row; if (r >= VV) r = VV - 1;
        size_t so = (size_t)r * KK + kg + c8 * 8;
        uint32_t dsw = SWZ((uint32_t)(row * 128 + c8 * 16));
        cpasync16(base + dsw, g_lw_hi + so);
        cpasync16(base + 16384 + dsw, g_lw_lo + so);
    }
}
__device__ __forceinline__ void stage_log_h(uint32_t sbase, int kc, int kg, int tid)
{
    uint32_t base = sbase + LH0 + (uint32_t)(kc & 1) * 16384;
#pragma unroll
    for (int i = 0; i < 4; i++) {
        int g = tid + i * 128;
        int row = g >> 3, c8 = g & 7;
        size_t so = (size_t)row * KK + kg + c8 * 8;
        uint32_t dsw = SWZ((uint32_t)(row * 128 + c8 * 16));
        cpasync16(base + dsw, g_hhi + so);
        cpasync16(base + 8192 + dsw, g_hlo + so);
    }
}

__device__ __forceinline__ void tc_pipe_log(
    uint32_t sbase, uint32_t tmem, int tile0, int ntiles, int tid, int wid)
{
    const int NCH = ntiles * NCHT;
    stage_log_w(sbase, 0, tile0 * NT, 0, tid);
    GDC_WAIT();
    stage_log_h(sbase, 0, 0, tid);
    asm volatile("cp.async.commit_group;" ::: "memory");
    for (int cc = 0; cc < NCH; cc++) {
        int tile = (ntiles == 2) ? (cc & 1) : 0;
        int kc = (ntiles == 2) ? (cc >> 1) : cc;
        if (cc + 1 < NCH) {
            int nc = cc + 1;
            int ntile = (ntiles == 2) ? (nc & 1) : 0;
            int nkc = (ntiles == 2) ? (nc >> 1) : nc;
            if (nc >= 2) {
                int idx = (cc - 1) >> 1;
                mbar_wait(sbase + 8 + (uint32_t)(nc & 1) * 8, (uint32_t)(idx & 1));
            }
            stage_log_w(sbase, nc, (tile0 + ntile) * NT, nkc * KB, tid);
            if (ntile == 0 && nkc > 0) stage_log_h(sbase, nkc, nkc * KB, tid);
            asm volatile("cp.async.commit_group;" ::: "memory");
            asm volatile("cp.async.wait_group 1;" ::: "memory");
        } else {
            asm volatile("cp.async.wait_group 0;" ::: "memory");
        }
        __syncthreads();
        if (wid == 0) {
            uint32_t is1;
            asm volatile("{ .reg .pred p; elect.sync _|p, 0xFFFFFFFF; selp.b32 %0,1,0,p; }" : "=r"(is1));
            if (is1) {
                uint32_t wOff = LW0 + (uint32_t)(cc & 1) * 32768;
                uint32_t hOff = LH0 + (uint32_t)(kc & 1) * 16384;
                mma3_at(sbase, tmem + (uint32_t)tile * 64, cc, wOff, hOff, kc == 0);
            }
        }
    }
    uint32_t fp = (uint32_t)(((NCH / 2) - 1) & 1);
    mbar_wait(sbase + 8, fp);
    mbar_wait(sbase + 16, fp);
    asm volatile("tcgen05.fence::after_thread_sync;" ::: "memory");
}

#define TC_PROLOG(sbase, tmem, ncols)                                                        \
    if (wid == 0) {                                                                          \
        asm volatile("tcgen05.alloc.cta_group::1.sync.aligned.shared::cta.b32 [%0], %1;"     \
                     :: "r"(sbase), "r"((uint32_t)(ncols)) : "memory");                      \
        asm volatile("tcgen05.relinquish_alloc_permit.cta_group::1.sync.aligned;");          \
    }                                                                                        \
    if (tid == 0) {                                                                          \
        asm volatile("mbarrier.init.shared.b64 [%0], %1;" :: "r"(sbase + 8), "r"(1u) : "memory");  \
        asm volatile("mbarrier.init.shared.b64 [%0], %1;" :: "r"(sbase + 16), "r"(1u) : "memory"); \
    }                                                                                        \
    __syncthreads();                                                                         \
    asm volatile("ld.shared.b32 %0, [%1];" : "=r"(tmem) : "r"(sbase));

#define TC_EPILOG(sbase, tmem, ncols)                                                        \
    __syncthreads();                                                                         \
    if (tid == 0) {                                                                          \
        asm volatile("mbarrier.inval.shared.b64 [%0];" :: "r"(sbase + 8) : "memory");        \
        asm volatile("mbarrier.inval.shared.b64 [%0];" :: "r"(sbase + 16) : "memory");       \
    }                                                                                        \
    __syncthreads();                                                                         \
    if (wid == 0)                                                                            \
        asm volatile("tcgen05.dealloc.cta_group::1.sync.aligned.b32 %0, %1;" :: "r"(tmem), "r"((uint32_t)(ncols)));

#define LDTM32(r, addr) \
    asm volatile("tcgen05.ld.sync.aligned.32x32b.x32.b32 " \
        "{%0,%1,%2,%3,%4,%5,%6,%7,%8,%9,%10,%11,%12,%13,%14,%15," \
        "%16,%17,%18,%19,%20,%21,%22,%23,%24,%25,%26,%27,%28,%29,%30,%31}, [%32];" \
        : "=r"((r)[0]),"=r"((r)[1]),"=r"((r)[2]),"=r"((r)[3]),"=r"((r)[4]),"=r"((r)[5]),"=r"((r)[6]),"=r"((r)[7]), \
          "=r"((r)[8]),"=r"((r)[9]),"=r"((r)[10]),"=r"((r)[11]),"=r"((r)[12]),"=r"((r)[13]),"=r"((r)[14]),"=r"((r)[15]), \
          "=r"((r)[16]),"=r"((r)[17]),"=r"((r)[18]),"=r"((r)[19]),"=r"((r)[20]),"=r"((r)[21]),"=r"((r)[22]),"=r"((r)[23]), \
          "=r"((r)[24]),"=r"((r)[25]),"=r"((r)[26]),"=r"((r)[27]),"=r"((r)[28]),"=r"((r)[29]),"=r"((r)[30]),"=r"((r)[31]) \
        : "r"(addr))
#endif // HAS_TC

// ------------------------- small kernels ----------------------------------
__global__ void prep_lw_kernel(const float* __restrict__ lin_w)
{
    const size_t NW = (size_t)VV * KK / 4;
    size_t i = (size_t)blockIdx.x * 256 + threadIdx.x;
    if (i >= NW) return;
    float4 v = ((const float4*)lin_w)[i];
    uint2 hp, lp;
    hp.x = packbf2(v.x, v.y);
    hp.y = packbf2(v.z, v.w);
    float r0 = v.x - __bfloat162float(__float2bfloat16(v.x));
    float r1 = v.y - __bfloat162float(__float2bfloat16(v.y));
    float r2 = v.z - __bfloat162float(__float2bfloat16(v.z));
    float r3 = v.w - __bfloat162float(__float2bfloat16(v.w));
    lp.x = packbf2(r0, r1);
    lp.y = packbf2(r2, r3);
    *(uint2*)(g_lw_hi + i * 4) = hp;
    *(uint2*)(g_lw_lo + i * 4) = lp;
}

__global__ void prep_gru_kernel(const float* __restrict__ w_ih,
                                const float* __restrict__ w_hh)
{
    const size_t NG = (size_t)G3 * KK / 4;
    size_t i = (size_t)blockIdx.x * 256 + threadIdx.x;
    const float* src; __nv_bfloat16 *dhi, *dlo; size_t off;
    if (i < NG)          { src = w_ih; dhi = g_wi_hi; dlo = g_wi_lo; off = i; }
    else if (i < 2 * NG) { src = w_hh; dhi = g_wh_hi; dlo = g_wh_lo; off = i - NG; }
    else return;
    float4 v = ((const float4*)src)[off];
    uint2 hp, lp;
    hp.x = packbf2(v.x, v.y);
    hp.y = packbf2(v.z, v.w);
    float r0 = v.x - __bfloat162float(__float2bfloat16(v.x));
    float r1 = v.y - __bfloat162float(__float2bfloat16(v.y));
    float r2 = v.z - __bfloat162float(__float2bfloat16(v.z));
    float r3 = v.w - __bfloat162float(__float2bfloat16(v.w));
    lp.x = packbf2(r0, r1);
    lp.y = packbf2(r2, r3);
    *(uint2*)(dhi + off * 4) = hp;
    *(uint2*)(dlo + off * 4) = lp;
}

__global__ void init_kernel(const int* __restrict__ target,
                            const float* __restrict__ enc)
{
    int i = blockIdx.x * 256 + threadIdx.x;
    if (i < BB) g_x[i] = target[i * TT];
    if (i < BB * HH) {
        float h = enc[i];
        g_h[i] = h;
        __nv_bfloat16 hb = __float2bfloat16(h);
        g_hhi[i] = hb;
        g_hlo[i] = __float2bfloat16(h - __bfloat162float(hb));
    }
}

// ------------------------- GRU GEMM ----------------------------------------
__global__ void __launch_bounds__(128) gru_tc_kernel(
    const float* __restrict__ w_ih, const float* __restrict__ w_hh,
    const float* __restrict__ emb)
{
    const int tid = threadIdx.x, wid = tid >> 5;
    const int z = blockIdx.z, ksl = blockIdx.y;
    const int row0 = blockIdx.x * 128;
    GDC_LAUNCH();
#if HAS_TC
    extern __shared__ char smem[];
    uint32_t sbase = smem_u32(smem);
    uint32_t tmem;
    TC_PROLOG(sbase, tmem, 64);
    if (z) {
        tc_pipe_gru<NCH_G, false>(smem, sbase, tmem, g_wh_hi, g_wh_lo,
                                  g_hhi, g_hlo, (const float*)0,
                                  row0, ksl * KC, tid, wid);
    } else {
        tc_pipe_gru<NCH_G, true>(smem, sbase, tmem, g_wi_hi, g_wi_lo,
                                 (const __nv_bfloat16*)0, (const __nv_bfloat16*)0, emb,
                                 row0, ksl * KC, tid, wid);
    }

    uint32_t d0[32], d1[32];
    LDTM32(d0, tmem);
    LDTM32(d1, tmem + 32);
    asm volatile("tcgen05.wait::ld.sync.aligned;" ::: "memory");

    float* out = (z ? g_gh : g_gi) + ksl * (BB * G3);
    int n = row0 + tid;
#pragma unroll
    for (int m = 0; m < 32; m++) out[m * G3 + n] = __uint_as_float(d0[m]);
#pragma unroll
    for (int m = 0; m < 32; m++) out[(m + 32) * G3 + n] = __uint_as_float(d1[m]);

    TC_EPILOG(sbase, tmem, 64);
#else
    GDC_WAIT();
    const float* A = z ? g_h : emb;
    const float* W = z ? w_hh : w_ih;
    float* out = (z ? g_gh : g_gi) + ksl * (BB * G3);
    ull acc[8][4];
    gemm_core(A, W, row0, ksl * KC, KC, G3, acc, z ? (const int*)0 : g_x);
    int v_idx = tid & 15, m_idx = tid >> 4;
#pragma unroll
    for (int i = 0; i < 8; i++) {
        int m = m_idx * 8 + i;
#pragma unroll
        for (int p = 0; p < 4; p++) {
            float lo, hi; upk2(acc[i][p], lo, hi);
            int n = row0 + v_idx * 8 + p * 2;
            *(float2*)(out + m * G3 + n) = make_float2(lo, hi);
        }
    }
#endif
}

// split-K reduce + GRU gates + h update + bf16 split of h
__global__ void gate_kernel(const float* __restrict__ b_ih,
                            const float* __restrict__ b_hh)
{
    GDC_WAIT();
    GDC_LAUNCH();
    int i = blockIdx.x * 256 + threadIdx.x;
    if (i >= BB * HH) return;
    int m = i >> 10, j = i & 1023;
    float gir = 0, giz = 0, gin = 0, ghr = 0, ghz = 0, ghn = 0;
#pragma unroll
    for (int s = 0; s < SPLITK; s++) {
        const float* gi = g_gi + s * BB * G3 + m * G3;
        const float* gh = g_gh + s * BB * G3 + m * G3;
        gir += gi[j]; giz += gi[HH + j]; gin += gi[2 * HH + j];
        ghr += gh[j]; ghz += gh[HH + j]; ghn += gh[2 * HH + j];
    }
    gir += b_ih[j]; giz += b_ih[HH + j]; gin += b_ih[2 * HH + j];
    ghr += b_hh[j]; ghz += b_hh[HH + j]; ghn += b_hh[2 * HH + j];
    float r = 1.f / (1.f + expf(-(gir + ghr)));
    float z = 1.f / (1.f + expf(-(giz + ghz)));
    float n = tanhf(gin + r * ghn);
    float hn = (1.f - z) * n + z * g_h[i];
    g_h[i] = hn;
    __nv_bfloat16 hb = __float2bfloat16(hn);
    g_hhi[i] = hb;
    g_hlo[i] = __float2bfloat16(hn - __bfloat162float(hb));
}

// ------------------------- logits ------------------------------------------
__global__ void __launch_bounds__(128) logits_tc_kernel(
    const float* __restrict__ lin_w, const float* __restrict__ lin_b,
    float* __restrict__ logits, int t)
{
    const int tile0 = blockIdx.x * 2;
    const int ntiles = (tile0 + 1 < NBLKV) ? 2 : 1;
    GDC_LAUNCH();
#if HAS_TC
    extern __shared__ char smem[];
    uint32_t sbase = smem_u32(smem);
    const int tid = threadIdx.x, wid = tid >> 5;
    uint32_t tmem;
    TC_PROLOG(sbase, tmem, 128);

    tc_pipe_log(sbase, tmem, tile0, ntiles, tid, wid);

    for (int sub = 0; sub < ntiles; sub++) {
        const int tile = tile0 + sub;
        const int n0 = tile * NT;
        const int v = n0 + tid;
        const bool valid = v < VV;
        float bias = lin_b[valid ? v : VV - 1];
        uint32_t d0[32], d1[32];
        LDTM32(d0, tmem + (uint32_t)sub * 64);
        LDTM32(d1, tmem + (uint32_t)sub * 64 + 32);
        asm volatile("tcgen05.wait::ld.sync.aligned;" ::: "memory");

        float vals[64];
#pragma unroll
        for (int j = 0; j < 32; j++) {
            vals[j] = __uint_as_float(d0[j]) + bias;
            vals[32 + j] = __uint_as_float(d1[j]) + bias;
        }

#pragma unroll
        for (int m = 0; m < 64; m++)
            if (valid) logits[((size_t)m * TT + t) * VV + v] = vals[m];

        float* ts = (float*)(smem + LW0);
        __syncthreads();
#pragma unroll
        for (int m = 0; m < 64; m++)
            ts[tid * 65 + m] = valid ? vals[m] : -INFINITY;
        __syncthreads();

        int m = tid >> 1, half = tid & 1;
        float best = -INFINITY; int bi = 0;
        for (int j = 0; j < 64; j++) {
            float x = ts[(half * 64 + j) * 65 + m];
            if (x > best) { best = x; bi = half * 64 + j; }
        }
        float s = 0.f;
        if (best > -INFINITY)
            for (int j = 0; j < 64; j++)
                s += __expf(ts[(half * 64 + j) * 65 + m] - best);

        float ob = __shfl_xor_sync(0xffffffffu, best, 1);
        int   oi = __shfl_xor_sync(0xffffffffu, bi, 1);
        float os = __shfl_xor_sync(0xffffffffu, s, 1);
        float M2 = fmaxf(best, ob);
        float S2 = 0.f;
        if (best > -INFINITY) S2 += s * __expf(best - M2);
        if (ob   > -INFINITY) S2 += os * __expf(ob - M2);
        int gbi = bi;
        if (ob > best || (ob == best && oi < bi)) gbi = oi;
        if (half == 0) {
            g_pmax[tile * BB + m] = M2;
            g_pidx[tile * BB + m] = n0 + gbi;
            g_psum[tile * BB + m] = S2;
        }
    }

    TC_EPILOG(sbase, tmem, 128);
#else
    GDC_WAIT();
    for (int sub = 0; sub < ntiles; sub++) {
        int tile = tile0 + sub;
        if (tile >= NBLKV) break;
        int n0 = tile * NT;
        ull acc[8][4];
        gemm_core(g_h, lin_w, n0, 0, KK, VV, acc, (const int*)0);
        int v_idx = threadIdx.x & 15, m_idx = threadIdx.x >> 4;
        int vb = n0 + v_idx * 8;

        float bias[8];
#pragma unroll
        for (int j = 0; j < 8; j++) {
            int v = vb + j;
            bias[j] = lin_b[v < VV ? v : VV - 1];
        }

#pragma unroll
        for (int i = 0; i < 8; i++) {
            int m = m_idx * 8 + i;
            float vals[8];
#pragma unroll
            for (int p = 0; p < 4; p++) {
                float lo, hi; upk2(acc[i][p], lo, hi);
                vals[p * 2]     = lo + bias[p * 2];
                vals[p * 2 + 1] = hi + bias[p * 2 + 1];
            }
            size_t base = ((size_t)m * TT + t) * VV;
#pragma unroll
            for (int j = 0; j < 8; j++) {
                int v = vb + j;
                if (v < VV) logits[base + v] = vals[j];
            }
            float vmax = -INFINITY; int vidx = 0;
#pragma unroll
            for (int j = 0; j < 8; j++) {
                int v = vb + j;
                if (v < VV && vals[j] > vmax) { vmax = vals[j]; vidx = v; }
            }
            float ssum = 0.f;
            if (vmax > -INFINITY) {
#pragma unroll
                for (int j = 0; j < 8; j++) {
                    int v = vb + j;
                    if (v < VV) ssum += expf(vals[j] - vmax);
                }
            }
#pragma unroll
            for (int off = 8; off >= 1; off >>= 1) {
                float om = __shfl_xor_sync(0xffffffffu, vmax, off);
                int   oi = __shfl_xor_sync(0xffffffffu, vidx, off);
                float os = __shfl_xor_sync(0xffffffffu, ssum, off);
                float nm = fmaxf(vmax, om);
                float ns = 0.f;
                if (vmax > -INFINITY) ns += ssum * expf(vmax - nm);
                if (om   > -INFINITY) ns += os   * expf(om  - nm);
                if (om > vmax || (om == vmax && oi < vidx)) vidx = oi;
                vmax = nm; ssum = ns;
            }
            if (v_idx == 0) {
                g_pmax[tile * BB + m] = vmax;
                g_pidx[tile * BB + m] = vidx;
                g_psum[tile * BB + m] = ssum;
            }
        }
        __syncthreads();
    }
#endif
}

// per-m reduce of block partials -> argmax token + lse (double buffered)
__global__ void __launch_bounds__(128) reduce_kernel(int par)
{
    GDC_WAIT();
    GDC_LAUNCH();
    int m = blockIdx.x;
    int tid = threadIdx.x;
    float M = -INFINITY, S = 0.f, bv = -INFINITY; int bi = 0;
    for (int b = tid; b < NBLKV; b += 128) {
        float pm = g_pmax[b * BB + m];
        int   pi = g_pidx[b * BB + m];
        float ps = g_psum[b * BB + m];
        if (pm > bv || (pm == bv && pi < bi)) { bv = pm; bi = pi; }
        float nm = fmaxf(M, pm);
        float ns = 0.f;
        if (M  > -INFINITY) ns += S  * expf(M  - nm);
        if (pm > -INFINITY) ns += ps * expf(pm - nm);
        M = nm; S = ns;
    }
    __shared__ float sM[128], sS[128], sV[128];
    __shared__ int sI[128];
    sM[tid] = M; sS[tid] = S; sV[tid] = bv; sI[tid] = bi;
    __syncthreads();
    for (int w = 64; w >= 1; w >>= 1) {
        if (tid < w) {
            float om = sM[tid + w], os = sS[tid + w], ov = sV[tid + w];
            int oi = sI[tid + w];
            if (ov > sV[tid] || (ov == sV[tid] && oi < sI[tid])) { sV[tid] = ov; sI[tid] = oi; }
            float nm = fmaxf(sM[tid], om);
            float ns = 0.f;
            if (sM[tid] > -INFINITY) ns += sS[tid] * expf(sM[tid] - nm);
            if (om      > -INFINITY) ns += os      * expf(om      - nm);
            sM[tid] = nm; sS[tid] = ns;
        }
        __syncthreads();
    }
    if (tid == 0) { g_x[m] = sI[0]; g_lse[par * BB + m] = sM[0] + logf(sS[0]); }
}

// logp writer (side stream; off the recurrence critical path)
#define VCHK 3968
#define NVCHK ((VV + VCHK - 1) / VCHK)   // 13
__global__ void __launch_bounds__(256) logp_kernel(
    const float* __restrict__ logits, float* __restrict__ logp, int t, int par)
{
    const int m = blockIdx.y;
    const int ck = blockIdx.x;
    const int tid = threadIdx.x;
    float lse = g_lse[par * BB + m];
    size_t base = ((size_t)m * TT + t) * VV;
    int vend = (ck + 1) * VCHK; if (vend > VV) vend = VV;
    for (int v = ck * VCHK + tid; v < vend; v += 256)
        logp[base + v] = logits[base + v] - lse;
}

// ------------------------- launch -----------------------------------------
extern "C" void kernel_launch(void* const* d_in, const int* in_sizes, int n_in,
                              void* d_out, int out_size)
{
    const int*   target = (const int*)  d_in[0];
    const float* enc    = (const float*)d_in[1];
    const float* emb    = (const float*)d_in[2];
    const float* w_ih   = (const float*)d_in[3];
    const float* w_hh   = (const float*)d_in[4];
    const float* b_ih   = (const float*)d_in[5];
    const float* b_hh   = (const float*)d_in[6];
    const float* lin_w  = (const float*)d_in[7];
    const float* lin_b  = (const float*)d_in[8];

    float* logp   = (float*)d_out;                 // (B, T, V)
    float* logits = logp + (size_t)BB * TT * VV;   // (B, T, V)

    // one-time resource setup (no allocations during the captured call)
    static cudaStream_t s2;
    static cudaEvent_t e0, eLw, eFork, eJoin;
    static int inited = 0;
    if (!inited) {
        cudaFuncSetAttribute(logits_tc_kernel,
                             cudaFuncAttributeMaxDynamicSharedMemorySize, SM_TC);
        cudaFuncSetAttribute(gru_tc_kernel,
                             cudaFuncAttributeMaxDynamicSharedMemorySize, SM_TC);
        cudaStreamCreateWithFlags(&s2, cudaStreamNonBlocking);
        cudaEventCreateWithFlags(&e0, cudaEventDisableTiming);
        cudaEventCreateWithFlags(&eLw, cudaEventDisableTiming);
        cudaEventCreateWithFlags(&eFork, cudaEventDisableTiming);
        cudaEventCreateWithFlags(&eJoin, cudaEventDisableTiming);
        inited = 1;
    }

    cudaLaunchAttribute pdlAttr[1];
    pdlAttr[0].id = cudaLaunchAttributeProgrammaticStreamSerialization;
    pdlAttr[0].val.programmaticStreamSerializationAllowed = 1;

    // fork: lin_w prep on s2
    cudaEventRecord(e0, 0);
    cudaStreamWaitEvent(s2, e0, 0);
    const size_t nw4 = (size_t)VV * KK / 4;
    prep_lw_kernel<<<(unsigned)((nw4 + 255) / 256), 256, 0, s2>>>(lin_w);
    cudaEventRecord(eLw, s2);

    const size_t ng4 = 2 * (size_t)G3 * KK / 4;
    prep_gru_kernel<<<(unsigned)((ng4 + 255) / 256), 256>>>(w_ih, w_hh);
    init_kernel<<<(BB * HH + 255) / 256, 256>>>(target, enc);

    for (int t = 0; t < TT; t++) {
        {
            cudaLaunchConfig_t cfg = {};
            cfg.gridDim = dim3(G3 / NT, SPLITK, 2);
            cfg.blockDim = dim3(128);
            cfg.dynamicSmemBytes = SM_TC;
            cfg.stream = 0;
            cfg.attrs = pdlAttr; cfg.numAttrs = 1;
            cudaLaunchKernelEx(&cfg, gru_tc_kernel, w_ih, w_hh, emb);
        }
        {
            cudaLaunchConfig_t cfg = {};
            cfg.gridDim = dim3((BB * HH + 255) / 256);
            cfg.blockDim = dim3(256);
            cfg.stream = 0;
            cfg.attrs = pdlAttr; cfg.numAttrs = 1;
            cudaLaunchKernelEx(&cfg, gate_kernel, b_ih, b_hh);
        }
        if (t == 0) cudaStreamWaitEvent(0, eLw, 0);
        {
            cudaLaunchConfig_t cfg = {};
            cfg.gridDim = dim3(NBLK2);
            cfg.blockDim = dim3(128);
            cfg.dynamicSmemBytes = SM_TC;
            cfg.stream = 0;
            cfg.attrs = pdlAttr; cfg.numAttrs = 1;
            cudaLaunchKernelEx(&cfg, logits_tc_kernel, lin_w, lin_b, logits, t);
        }
        {
            cudaLaunchConfig_t cfg = {};
            cfg.gridDim = dim3(BB);
            cfg.blockDim = dim3(128);
            cfg.stream = 0;
            cfg.attrs = pdlAttr; cfg.numAttrs = 1;
            int par = t & 1;
            cudaLaunchKernelEx(&cfg, reduce_kernel, par);
        }
        // fork logp write to s2 (R13-measured-best placement)
        cudaEventRecord(eFork, 0);
        cudaStreamWaitEvent(s2, eFork, 0);
        logp_kernel<<<dim3(NVCHK, BB), 256, 0, s2>>>(logits, logp, t, t & 1);
        cudaEventRecord(eJoin, s2);
    }
    cudaStreamWaitEvent(0, eJoin, 0);
}